// round 3
// baseline (speedup 1.0000x reference)
#include <cuda_runtime.h>

#define BM 128
#define BN 128
#define BK 32          // 4 input features x 8 basis per K-tile
#define TM 8
#define TN 8
#define IN_COUNT 512
#define NB 8
#define OUT_COUNT 512
#define BATCH 8192
#define KTOT (IN_COUNT * NB)   // 4096

// ---- packed f32x2 helpers (FFMA2: PTX-only path, 2x FFMA throughput) ----
__device__ __forceinline__ unsigned long long pack2_dup(float v) {
    unsigned long long r;
    asm("mov.b64 %0, {%1, %1};" : "=l"(r) : "f"(v));
    return r;
}
__device__ __forceinline__ void fma2(unsigned long long& d,
                                     unsigned long long a,
                                     unsigned long long b) {
    asm("fma.rn.f32x2 %0, %1, %2, %0;" : "+l"(d) : "l"(a), "l"(b));
}
__device__ __forceinline__ void unpack2(unsigned long long v, float& lo, float& hi) {
    asm("mov.b64 {%0, %1}, %2;" : "=f"(lo), "=f"(hi) : "l"(v));
}

__global__ __launch_bounds__(256, 2)
void tanh_basis_fused_kernel(const float* __restrict__ x,
                             const float* __restrict__ coeffs,
                             const float* __restrict__ centers,
                             const float* __restrict__ slopes,
                             float* __restrict__ out)
{
    __shared__ __align__(16) float Bs[BK][BM];       // basis tile, [k][b]
    __shared__ __align__(16) float Cs[BK][BN + 2];   // coeff tile, [k][j], pad->stride 130 (even: keeps 8B align, kills worst conflicts)
    __shared__ float xs[BM * 4];                     // x tile: [b][i_local]
    __shared__ float cs[BK];                         // centers for current 4 i's (k-linear)
    __shared__ float ss[BK];                         // slopes  for current 4 i's

    const int tid = threadIdx.x;
    const int tx = tid & 15;        // 16 thread cols
    const int ty = tid >> 4;        // 16 thread rows
    const int b0 = blockIdx.x * BM;
    const int j0 = blockIdx.y * BN;

    unsigned long long acc2[TM][TN / 2];
    #pragma unroll
    for (int r = 0; r < TM; r++)
        #pragma unroll
        for (int c = 0; c < TN / 2; c++)
            acc2[r][c] = 0ull;      // bit pattern 0 == {0.0f, 0.0f}

    for (int k0 = 0; k0 < KTOT; k0 += BK) {
        const int i0 = k0 >> 3;   // 4 input features this tile: i0..i0+3

        // ---- stage x tile: 128 b x 4 i = 512 floats (2 waves of 256 threads) ----
        #pragma unroll
        for (int it = 0; it < 2; it++) {
            int t = it * 256 + tid;
            int b = t >> 2, il = t & 3;
            xs[t] = x[(b0 + b) * IN_COUNT + i0 + il];
        }
        // ---- stage centers/slopes: 32 contiguous floats each ----
        if (tid < BK) {
            cs[tid] = centers[i0 * NB + tid];
            ss[tid] = slopes[i0 * NB + tid];
        }
        // ---- stage coeff tile: Cs[k][j], coalesced reads over k ----
        #pragma unroll
        for (int it = 0; it < 16; it++) {
            int idx = it * 256 + tid;
            int j = idx >> 5, kk = idx & 31;
            Cs[kk][j] = coeffs[(j0 + j) * KTOT + k0 + kk];
        }
        __syncthreads();

        // ---- compute basis tile: s = sigmoid(2*gamma*(x-c)) = 0.5*(1+tanh(gamma*(x-c))) ----
        // exp never overflows (|2*gamma*(x-c)| <= 42), saturation handled naturally.
        #pragma unroll
        for (int it = 0; it < 16; it++) {
            int idx = it * 256 + tid;      // idx = k*128 + b  -> conflict-free stores
            int k = idx >> 7, b = idx & 127;
            float xv = xs[b * 4 + (k >> 3)];
            float z = ss[k] * (xv - cs[k]);
            float e = __expf(-2.0f * z);
            Bs[k][b] = __fdividef(1.0f, 1.0f + e);
        }
        __syncthreads();

        // ---- 128x128x32 FMA micro-kernel, packed f32x2 ----
        #pragma unroll 4
        for (int k = 0; k < BK; k++) {
            float a[TM];
            // vectorized basis loads (16B-aligned, 2 distinct addrs/warp -> broadcast)
            float4 av0 = *reinterpret_cast<const float4*>(&Bs[k][ty * TM]);
            float4 av1 = *reinterpret_cast<const float4*>(&Bs[k][ty * TM + 4]);
            a[0] = av0.x; a[1] = av0.y; a[2] = av0.z; a[3] = av0.w;
            a[4] = av1.x; a[5] = av1.y; a[6] = av1.z; a[7] = av1.w;

            unsigned long long a2[TM];
            #pragma unroll
            for (int r = 0; r < TM; r++) a2[r] = pack2_dup(a[r]);

            unsigned long long b2[TN / 2];
            #pragma unroll
            for (int c = 0; c < TN / 2; c++)
                b2[c] = *reinterpret_cast<const unsigned long long*>(&Cs[k][tx * TN + 2 * c]);

            #pragma unroll
            for (int r = 0; r < TM; r++)
                #pragma unroll
                for (int c = 0; c < TN / 2; c++)
                    fma2(acc2[r][c], a2[r], b2[c]);
        }
        __syncthreads();
    }

    // ---- epilogue ----
    #pragma unroll
    for (int r = 0; r < TM; r++) {
        int b = b0 + ty * TM + r;
        #pragma unroll
        for (int c = 0; c < TN / 2; c++) {
            float lo, hi;
            unpack2(acc2[r][c], lo, hi);
            int j = j0 + tx * TN + 2 * c;
            out[b * OUT_COUNT + j] = lo;
            out[b * OUT_COUNT + j + 1] = hi;
        }
    }
}

extern "C" void kernel_launch(void* const* d_in, const int* in_sizes, int n_in,
                              void* d_out, int out_size) {
    const float* x       = (const float*)d_in[0];
    const float* coeffs  = (const float*)d_in[1];
    const float* centers = (const float*)d_in[2];
    const float* slopes  = (const float*)d_in[3];
    float* out = (float*)d_out;

    dim3 grid(BATCH / BM, OUT_COUNT / BN);   // 64 x 4 = 256 blocks
    tanh_basis_fused_kernel<<<grid, 256>>>(x, coeffs, centers, slopes, out);
}

// round 8
// speedup vs baseline: 2.9114x; 2.9114x over previous
#include <cuda_runtime.h>
#include <cuda_bf16.h>
#include <cstdint>

#define IN_COUNT 512
#define NB 8
#define OUT_COUNT 512
#define BATCH 8192
#define KTOT 4096            // 512 * 8
#define BK 32                // 4 input features x 8 bases per chunk
#define NCHUNK (KTOT / BK)   // 128
#define BM 128
#define BN 128

#define PITCH 40                     // bf16 elems per smem row (80B) -> conflict-free frag LDS
#define TILE_BYTES (128 * PITCH * 2) // 10240 per array (A and B are both 128 rows here)
#define OFF_AH 0
#define OFF_AL (1 * TILE_BYTES)
#define OFF_BH (2 * TILE_BYTES)
#define OFF_BL (3 * TILE_BYTES)
#define STAGE_BYTES (4 * TILE_BYTES) // 40960
#define SMEM_BYTES (2 * STAGE_BYTES) // 81920

// ---- device scratch: bf16 hi/lo split of coeffs, [N=512][K=4096] K-major ----
__device__ __align__(16) __nv_bfloat16 g_ch[OUT_COUNT * KTOT];
__device__ __align__(16) __nv_bfloat16 g_cl[OUT_COUNT * KTOT];

// ===================== helpers =====================
__device__ __forceinline__ uint32_t smem_u32(const void* p) {
    uint32_t a;
    asm("{ .reg .u64 t; cvta.to.shared.u64 t, %1; cvt.u32.u64 %0, t; }" : "=r"(a) : "l"(p));
    return a;
}
// pack two f32 -> bf16x2 (e0 in LOW half / lower address)
__device__ __forceinline__ uint32_t pbf2(float e0, float e1) {
    uint32_t r;
    asm("cvt.rn.bf16x2.f32 %0, %1, %2;" : "=r"(r) : "f"(e1), "f"(e0));
    return r;
}
__device__ __forceinline__ float ex2(float x) {
    float y; asm("ex2.approx.f32 %0, %1;" : "=f"(y) : "f"(x)); return y;
}
__device__ __forceinline__ float frcp(float x) {
    float y; asm("rcp.approx.f32 %0, %1;" : "=f"(y) : "f"(x)); return y;
}
__device__ __forceinline__ void cp16(uint32_t dst_smem, const void* src) {
    asm volatile("cp.async.cg.shared.global [%0], [%1], 16;" :: "r"(dst_smem), "l"(src) : "memory");
}
__device__ __forceinline__ void mma16816(float* d, const uint32_t* a, const uint32_t* b) {
    asm volatile(
        "mma.sync.aligned.m16n8k16.row.col.f32.bf16.bf16.f32 "
        "{%0,%1,%2,%3}, {%4,%5,%6,%7}, {%8,%9}, {%0,%1,%2,%3};"
        : "+f"(d[0]), "+f"(d[1]), "+f"(d[2]), "+f"(d[3])
        : "r"(a[0]), "r"(a[1]), "r"(a[2]), "r"(a[3]), "r"(b[0]), "r"(b[1]));
}

// ===================== kernel 1: split coeffs into bf16 hi/lo =====================
__global__ void split_coeffs_kernel(const float* __restrict__ c) {
    int idx = blockIdx.x * blockDim.x + threadIdx.x;   // 512*4096/4 = 524288 float4 groups
    float4 v = reinterpret_cast<const float4*>(c)[idx];
    uint32_t h0 = pbf2(v.x, v.y);
    uint32_t h1 = pbf2(v.z, v.w);
    float hx = __uint_as_float(h0 << 16), hy = __uint_as_float(h0 & 0xffff0000u);
    float hz = __uint_as_float(h1 << 16), hw = __uint_as_float(h1 & 0xffff0000u);
    uint32_t l0 = pbf2(v.x - hx, v.y - hy);
    uint32_t l1 = pbf2(v.z - hz, v.w - hw);
    reinterpret_cast<uint2*>(g_ch)[idx] = make_uint2(h0, h1);
    reinterpret_cast<uint2*>(g_cl)[idx] = make_uint2(l0, l1);
}

// ===================== kernel 2: fused basis + split-bf16 mma.sync GEMM =====================
__global__ __launch_bounds__(256, 1)
void tanh_basis_mma_kernel(const float* __restrict__ x,
                           const float* __restrict__ centers,
                           const float* __restrict__ slopes,
                           float* __restrict__ out)
{
    extern __shared__ char smem[];
    const uint32_t sb32 = smem_u32(smem);
    const int tid  = threadIdx.x;
    const int lane = tid & 31;
    const int wid  = tid >> 5;
    const int g    = lane >> 2;         // fragment group id (row/col within 8)
    const int tg   = lane & 3;          // thread-in-group
    const int wm   = (wid & 3) * 32;    // warp m offset (4 warps over M)
    const int wn   = (wid >> 2) * 64;   // warp n offset (2 warps over N)
    const int b0   = blockIdx.x * BM;
    const int j0   = blockIdx.y * BN;

    const int il = tid & 3;             // feature lane within chunk (4 features)
    const int rb = tid >> 2;            // 0..63 -> rows rb, rb+64

    float acc[2][8][4];
    #pragma unroll
    for (int mt = 0; mt < 2; mt++)
        #pragma unroll
        for (int nt = 0; nt < 8; nt++)
            #pragma unroll
            for (int q = 0; q < 4; q++) acc[mt][nt][q] = 0.f;

    char* stg0 = smem;
    char* stg1 = smem + STAGE_BYTES;
    const float NEG2LOG2E = -2.885390081777927f;   // -2 * log2(e)

    uint32_t hp[2][4], lp[2][4];                   // staged basis regs (2 row-groups)

    // ---- stage B (coeff hi/lo) for chunk c via cp.async ----
    auto stage_B = [&](int c, char* stage) {
        uint32_t dH = smem_u32(stage) + OFF_BH;
        uint32_t dL = smem_u32(stage) + OFF_BL;
        #pragma unroll
        for (int r = 0; r < 2; r++) {
            int slot = r * 256 + tid;              // 512 slots of 16B per array
            int n = slot >> 2, kq = slot & 3;
            long go = (long)(j0 + n) * KTOT + c * BK + kq * 8;
            uint32_t doff = (uint32_t)(n * (PITCH * 2) + kq * 16);
            cp16(dH + doff, g_ch + go);
            cp16(dL + doff, g_cl + go);
        }
        asm volatile("cp.async.commit_group;" ::: "memory");
    };

    // ---- compute basis chunk c (sigmoid) into hp/lp registers ----
    auto compute_basis = [&](int c) {
        const int i = c * 4 + il;
        const float4 ct0 = __ldg(reinterpret_cast<const float4*>(&centers[i * NB]));
        const float4 ct1 = __ldg(reinterpret_cast<const float4*>(&centers[i * NB + 4]));
        const float4 sl0 = __ldg(reinterpret_cast<const float4*>(&slopes[i * NB]));
        const float4 sl1 = __ldg(reinterpret_cast<const float4*>(&slopes[i * NB + 4]));
        float km[8] = { NEG2LOG2E * sl0.x, NEG2LOG2E * sl0.y, NEG2LOG2E * sl0.z, NEG2LOG2E * sl0.w,
                        NEG2LOG2E * sl1.x, NEG2LOG2E * sl1.y, NEG2LOG2E * sl1.z, NEG2LOG2E * sl1.w };
        float kc[8] = { -km[0] * ct0.x, -km[1] * ct0.y, -km[2] * ct0.z, -km[3] * ct0.w,
                        -km[4] * ct1.x, -km[5] * ct1.y, -km[6] * ct1.z, -km[7] * ct1.w };
        #pragma unroll
        for (int r = 0; r < 2; r++) {
            const int row = rb + r * 64;
            const float xv = __ldg(&x[(long)(b0 + row) * IN_COUNT + i]);
            float sv[8];
            #pragma unroll
            for (int m = 0; m < 8; m++) {
                float e = ex2(fmaf(km[m], xv, kc[m]));     // exp(-2*gamma*(x-c))
                sv[m] = frcp(1.0f + e);                     // sigmoid
            }
            #pragma unroll
            for (int q = 0; q < 4; q++) {
                float a0 = sv[2 * q], a1 = sv[2 * q + 1];
                uint32_t h = pbf2(a0, a1);
                float h0 = __uint_as_float(h << 16);
                float h1 = __uint_as_float(h & 0xffff0000u);
                hp[r][q] = h;
                lp[r][q] = pbf2(a0 - h0, a1 - h1);
            }
        }
    };

    // ---- store staged basis into stage SMEM ----
    auto store_basis = [&](char* stage) {
        #pragma unroll
        for (int r = 0; r < 2; r++) {
            const int row = rb + r * 64;
            uint32_t doff = (uint32_t)(row * (PITCH * 2) + il * 16);   // 16B aligned (80*row + 16*il)
            *reinterpret_cast<uint4*>(stage + OFF_AH + doff) = make_uint4(hp[r][0], hp[r][1], hp[r][2], hp[r][3]);
            *reinterpret_cast<uint4*>(stage + OFF_AL + doff) = make_uint4(lp[r][0], lp[r][1], lp[r][2], lp[r][3]);
        }
    };

    // ---- MMA over one BK=32 stage (2 k16 steps) ----
    auto do_mma = [&](char* stage) {
        #pragma unroll
        for (int kk = 0; kk < 2; kk++) {
            const int kbB = kk * 16 * 2;    // byte offset along k
            uint32_t aH[2][4], aL[2][4];
            #pragma unroll
            for (int mt = 0; mt < 2; mt++) {
                const int m0 = wm + mt * 16;
                const char* pH = stage + OFF_AH + (m0 + g) * (PITCH * 2) + tg * 4 + kbB;
                const char* pL = stage + OFF_AL + (m0 + g) * (PITCH * 2) + tg * 4 + kbB;
                aH[mt][0] = *(const uint32_t*)(pH);
                aH[mt][1] = *(const uint32_t*)(pH + 8 * (PITCH * 2));
                aH[mt][2] = *(const uint32_t*)(pH + 16);
                aH[mt][3] = *(const uint32_t*)(pH + 8 * (PITCH * 2) + 16);
                aL[mt][0] = *(const uint32_t*)(pL);
                aL[mt][1] = *(const uint32_t*)(pL + 8 * (PITCH * 2));
                aL[mt][2] = *(const uint32_t*)(pL + 16);
                aL[mt][3] = *(const uint32_t*)(pL + 8 * (PITCH * 2) + 16);
            }
            #pragma unroll
            for (int nt = 0; nt < 8; nt++) {
                const int n0 = wn + nt * 8;
                const char* qH = stage + OFF_BH + (n0 + g) * (PITCH * 2) + tg * 4 + kbB;
                const char* qL = stage + OFF_BL + (n0 + g) * (PITCH * 2) + tg * 4 + kbB;
                uint32_t bH[2], bL[2];
                bH[0] = *(const uint32_t*)(qH);
                bH[1] = *(const uint32_t*)(qH + 16);
                bL[0] = *(const uint32_t*)(qL);
                bL[1] = *(const uint32_t*)(qL + 16);
                #pragma unroll
                for (int mt = 0; mt < 2; mt++) {
                    mma16816(acc[mt][nt], aH[mt], bH);   // hi*hi
                    mma16816(acc[mt][nt], aH[mt], bL);   // hi*lo
                    mma16816(acc[mt][nt], aL[mt], bH);   // lo*hi
                }
            }
        }
    };

    // ---- prologue: fill stage 0 ----
    stage_B(0, stg0);
    compute_basis(0);
    store_basis(stg0);
    asm volatile("cp.async.wait_group 0;" ::: "memory");
    __syncthreads();

    // ---- main loop ----
    for (int c = 0; c < NCHUNK; c++) {
        char* cur = (c & 1) ? stg1 : stg0;
        char* nxt = (c & 1) ? stg0 : stg1;
        if (c + 1 < NCHUNK) {
            stage_B(c + 1, nxt);     // async loads fly during MMA
            compute_basis(c + 1);    // MUFU overlaps HMMA (scheduled early, consumed late)
        }
        do_mma(cur);
        if (c + 1 < NCHUNK) {
            store_basis(nxt);
            asm volatile("cp.async.wait_group 0;" ::: "memory");
        }
        __syncthreads();
    }

    // ---- epilogue: write fp32 accumulators ----
    #pragma unroll
    for (int mt = 0; mt < 2; mt++) {
        #pragma unroll
        for (int nt = 0; nt < 8; nt++) {
            const int m = b0 + wm + mt * 16 + g;
            const int n = j0 + wn + nt * 8 + 2 * tg;
            *reinterpret_cast<float2*>(&out[(long)m * OUT_COUNT + n]) =
                make_float2(acc[mt][nt][0], acc[mt][nt][1]);
            *reinterpret_cast<float2*>(&out[(long)(m + 8) * OUT_COUNT + n]) =
                make_float2(acc[mt][nt][2], acc[mt][nt][3]);
        }
    }
}

// ===================== launch =====================
extern "C" void kernel_launch(void* const* d_in, const int* in_sizes, int n_in,
                              void* d_out, int out_size) {
    const float* x       = (const float*)d_in[0];
    const float* coeffs  = (const float*)d_in[1];
    const float* centers = (const float*)d_in[2];
    const float* slopes  = (const float*)d_in[3];
    float* out = (float*)d_out;

    cudaFuncSetAttribute(tanh_basis_mma_kernel,
                         cudaFuncAttributeMaxDynamicSharedMemorySize, SMEM_BYTES);

    split_coeffs_kernel<<<(OUT_COUNT * KTOT / 4) / 256, 256>>>(coeffs);

    dim3 grid(BATCH / BM, OUT_COUNT / BN);   // 64 x 4 = 256 CTAs
    tanh_basis_mma_kernel<<<grid, 256, SMEM_BYTES>>>(x, centers, slopes, out);
}

// round 11
// speedup vs baseline: 3.4533x; 1.1862x over previous
#include <cuda_runtime.h>
#include <cuda_bf16.h>
#include <cstdint>

#define IN_COUNT 512
#define NB 8
#define OUT_COUNT 512
#define BATCH 8192
#define KTOT 4096            // 512 * 8
#define BK 32                // 4 input features x 8 bases per chunk
#define NCHUNK (KTOT / BK)   // 128
#define BM 128
#define BN 256

#define PITCH 40                      // bf16 elems per smem row (80B) -> conflict-free frag LDS
#define TILE_A_BYTES (128 * PITCH * 2)   // 10240
#define TILE_B_BYTES (256 * PITCH * 2)   // 20480
#define OFF_AH 0
#define OFF_AL (TILE_A_BYTES)
#define OFF_BH (2 * TILE_A_BYTES)
#define OFF_BL (2 * TILE_A_BYTES + TILE_B_BYTES)
#define STAGE_BYTES (2 * TILE_A_BYTES + 2 * TILE_B_BYTES)  // 61440
#define SMEM_BYTES (2 * STAGE_BYTES)                        // 122880

// ---- device scratch: bf16 hi/lo split of coeffs, [N=512][K=4096] K-major ----
__device__ __align__(16) __nv_bfloat16 g_ch[OUT_COUNT * KTOT];
__device__ __align__(16) __nv_bfloat16 g_cl[OUT_COUNT * KTOT];

// ===================== helpers =====================
__device__ __forceinline__ uint32_t smem_u32(const void* p) {
    uint32_t a;
    asm("{ .reg .u64 t; cvta.to.shared.u64 t, %1; cvt.u32.u64 %0, t; }" : "=r"(a) : "l"(p));
    return a;
}
// pack two f32 -> bf16x2 (e0 in LOW half / lower address)
__device__ __forceinline__ uint32_t pbf2(float e0, float e1) {
    uint32_t r;
    asm("cvt.rn.bf16x2.f32 %0, %1, %2;" : "=r"(r) : "f"(e1), "f"(e0));
    return r;
}
__device__ __forceinline__ float ex2(float x) {
    float y; asm("ex2.approx.f32 %0, %1;" : "=f"(y) : "f"(x)); return y;
}
__device__ __forceinline__ float frcp(float x) {
    float y; asm("rcp.approx.f32 %0, %1;" : "=f"(y) : "f"(x)); return y;
}
__device__ __forceinline__ void cp16(uint32_t dst_smem, const void* src) {
    asm volatile("cp.async.cg.shared.global [%0], [%1], 16;" :: "r"(dst_smem), "l"(src) : "memory");
}
__device__ __forceinline__ void mma16816(float* d, const uint32_t* a, const uint32_t* b) {
    asm volatile(
        "mma.sync.aligned.m16n8k16.row.col.f32.bf16.bf16.f32 "
        "{%0,%1,%2,%3}, {%4,%5,%6,%7}, {%8,%9}, {%0,%1,%2,%3};"
        : "+f"(d[0]), "+f"(d[1]), "+f"(d[2]), "+f"(d[3])
        : "r"(a[0]), "r"(a[1]), "r"(a[2]), "r"(a[3]), "r"(b[0]), "r"(b[1]));
}

// ===================== kernel 1: split coeffs into bf16 hi/lo =====================
__global__ void split_coeffs_kernel(const float* __restrict__ c) {
    int idx = blockIdx.x * blockDim.x + threadIdx.x;   // 512*4096/4 = 524288 float4 groups
    float4 v = reinterpret_cast<const float4*>(c)[idx];
    uint32_t h0 = pbf2(v.x, v.y);
    uint32_t h1 = pbf2(v.z, v.w);
    float hx = __uint_as_float(h0 << 16), hy = __uint_as_float(h0 & 0xffff0000u);
    float hz = __uint_as_float(h1 << 16), hw = __uint_as_float(h1 & 0xffff0000u);
    uint32_t l0 = pbf2(v.x - hx, v.y - hy);
    uint32_t l1 = pbf2(v.z - hz, v.w - hw);
    reinterpret_cast<uint2*>(g_ch)[idx] = make_uint2(h0, h1);
    reinterpret_cast<uint2*>(g_cl)[idx] = make_uint2(l0, l1);
}

// ===================== kernel 2: fused basis + split-bf16 mma.sync GEMM =====================
__global__ __launch_bounds__(512, 1)
void tanh_basis_mma_kernel(const float* __restrict__ x,
                           const float* __restrict__ centers,
                           const float* __restrict__ slopes,
                           float* __restrict__ out)
{
    extern __shared__ char smem[];
    const int tid  = threadIdx.x;
    const int lane = tid & 31;
    const int wid  = tid >> 5;          // 0..15
    const int g    = lane >> 2;         // fragment group id
    const int tg   = lane & 3;          // thread-in-group
    const int wm   = (wid & 3) * 32;    // 4 warps over M (128)
    const int wn   = (wid >> 2) * 64;   // 4 warps over N (256)
    const int b0   = blockIdx.x * BM;
    const int j0   = blockIdx.y * BN;

    const int il = tid & 3;             // feature lane within chunk (4 features)
    const int rb = tid >> 2;            // 0..127: one A row per thread

    float acc[2][8][4];
    #pragma unroll
    for (int mt = 0; mt < 2; mt++)
        #pragma unroll
        for (int nt = 0; nt < 8; nt++)
            #pragma unroll
            for (int q = 0; q < 4; q++) acc[mt][nt][q] = 0.f;

    char* stg0 = smem;
    char* stg1 = smem + STAGE_BYTES;
    const float NEG2LOG2E = -2.885390081777927f;   // -2 * log2(e)

    uint32_t hp[4], lp[4];              // staged basis regs (one row per thread)

    // ---- stage B (coeff hi/lo) for chunk c via cp.async ----
    auto stage_B = [&](int c, char* stage) {
        uint32_t dH = smem_u32(stage) + OFF_BH;
        uint32_t dL = smem_u32(stage) + OFF_BL;
        #pragma unroll
        for (int r = 0; r < 2; r++) {
            int slot = r * 512 + tid;              // 1024 slots of 16B per array
            int n = slot >> 2, kq = slot & 3;
            long go = (long)(j0 + n) * KTOT + c * BK + kq * 8;
            uint32_t doff = (uint32_t)(n * (PITCH * 2) + kq * 16);
            cp16(dH + doff, g_ch + go);
            cp16(dL + doff, g_cl + go);
        }
        asm volatile("cp.async.commit_group;" ::: "memory");
    };

    // ---- compute basis chunk c (sigmoid) into hp/lp registers ----
    auto compute_basis = [&](int c) {
        const int i = c * 4 + il;
        const float4 ct0 = __ldg(reinterpret_cast<const float4*>(&centers[i * NB]));
        const float4 ct1 = __ldg(reinterpret_cast<const float4*>(&centers[i * NB + 4]));
        const float4 sl0 = __ldg(reinterpret_cast<const float4*>(&slopes[i * NB]));
        const float4 sl1 = __ldg(reinterpret_cast<const float4*>(&slopes[i * NB + 4]));
        float km[8] = { NEG2LOG2E * sl0.x, NEG2LOG2E * sl0.y, NEG2LOG2E * sl0.z, NEG2LOG2E * sl0.w,
                        NEG2LOG2E * sl1.x, NEG2LOG2E * sl1.y, NEG2LOG2E * sl1.z, NEG2LOG2E * sl1.w };
        float kc[8] = { -km[0] * ct0.x, -km[1] * ct0.y, -km[2] * ct0.z, -km[3] * ct0.w,
                        -km[4] * ct1.x, -km[5] * ct1.y, -km[6] * ct1.z, -km[7] * ct1.w };
        const float xv = __ldg(&x[(long)(b0 + rb) * IN_COUNT + i]);
        float sv[8];
        #pragma unroll
        for (int m = 0; m < 8; m++) {
            float e = ex2(fmaf(km[m], xv, kc[m]));     // exp(-2*gamma*(x-c))
            sv[m] = frcp(1.0f + e);                     // sigmoid
        }
        #pragma unroll
        for (int q = 0; q < 4; q++) {
            float a0 = sv[2 * q], a1 = sv[2 * q + 1];
            uint32_t h = pbf2(a0, a1);
            float h0 = __uint_as_float(h << 16);
            float h1 = __uint_as_float(h & 0xffff0000u);
            hp[q] = h;
            lp[q] = pbf2(a0 - h0, a1 - h1);
        }
    };

    // ---- store staged basis into stage SMEM ----
    auto store_basis = [&](char* stage) {
        uint32_t doff = (uint32_t)(rb * (PITCH * 2) + il * 16);
        *reinterpret_cast<uint4*>(stage + OFF_AH + doff) = make_uint4(hp[0], hp[1], hp[2], hp[3]);
        *reinterpret_cast<uint4*>(stage + OFF_AL + doff) = make_uint4(lp[0], lp[1], lp[2], lp[3]);
    };

    // ---- MMA over one BK=32 stage (2 k16 steps), phase-reordered to break acc RAW chains ----
    auto do_mma = [&](char* stage) {
        #pragma unroll
        for (int kk = 0; kk < 2; kk++) {
            const int kbB = kk * 32;        // byte offset along k
            uint32_t aH[2][4], aL[2][4];
            #pragma unroll
            for (int mt = 0; mt < 2; mt++) {
                const int m0 = wm + mt * 16;
                const char* pH = stage + OFF_AH + (m0 + g) * (PITCH * 2) + tg * 4 + kbB;
                const char* pL = stage + OFF_AL + (m0 + g) * (PITCH * 2) + tg * 4 + kbB;
                aH[mt][0] = *(const uint32_t*)(pH);
                aH[mt][1] = *(const uint32_t*)(pH + 8 * (PITCH * 2));
                aH[mt][2] = *(const uint32_t*)(pH + 16);
                aH[mt][3] = *(const uint32_t*)(pH + 8 * (PITCH * 2) + 16);
                aL[mt][0] = *(const uint32_t*)(pL);
                aL[mt][1] = *(const uint32_t*)(pL + 8 * (PITCH * 2));
                aL[mt][2] = *(const uint32_t*)(pL + 16);
                aL[mt][3] = *(const uint32_t*)(pL + 8 * (PITCH * 2) + 16);
            }
            // phase 1: hi*hi over all nt (16 independent MMAs)
            #pragma unroll
            for (int nt = 0; nt < 8; nt++) {
                const char* qH = stage + OFF_BH + (wn + nt * 8 + g) * (PITCH * 2) + tg * 4 + kbB;
                uint32_t bH[2] = { *(const uint32_t*)(qH), *(const uint32_t*)(qH + 16) };
                mma16816(acc[0][nt], aH[0], bH);
                mma16816(acc[1][nt], aH[1], bH);
            }
            // phase 2: hi*lo
            #pragma unroll
            for (int nt = 0; nt < 8; nt++) {
                const char* qL = stage + OFF_BL + (wn + nt * 8 + g) * (PITCH * 2) + tg * 4 + kbB;
                uint32_t bL[2] = { *(const uint32_t*)(qL), *(const uint32_t*)(qL + 16) };
                mma16816(acc[0][nt], aH[0], bL);
                mma16816(acc[1][nt], aH[1], bL);
            }
            // phase 3: lo*hi
            #pragma unroll
            for (int nt = 0; nt < 8; nt++) {
                const char* qH = stage + OFF_BH + (wn + nt * 8 + g) * (PITCH * 2) + tg * 4 + kbB;
                uint32_t bH[2] = { *(const uint32_t*)(qH), *(const uint32_t*)(qH + 16) };
                mma16816(acc[0][nt], aL[0], bH);
                mma16816(acc[1][nt], aL[1], bH);
            }
        }
    };

    // ---- prologue: fill stage 0 ----
    stage_B(0, stg0);
    compute_basis(0);
    store_basis(stg0);
    asm volatile("cp.async.wait_group 0;" ::: "memory");
    __syncthreads();

    // ---- main loop ----
    for (int c = 0; c < NCHUNK; c++) {
        char* cur = (c & 1) ? stg1 : stg0;
        char* nxt = (c & 1) ? stg0 : stg1;
        if (c + 1 < NCHUNK) {
            stage_B(c + 1, nxt);     // async loads fly during MMA
            compute_basis(c + 1);    // MUFU overlaps HMMA
        }
        do_mma(cur);
        if (c + 1 < NCHUNK) {
            store_basis(nxt);
            asm volatile("cp.async.wait_group 0;" ::: "memory");
        }
        __syncthreads();
    }

    // ---- epilogue: write fp32 accumulators ----
    #pragma unroll
    for (int mt = 0; mt < 2; mt++) {
        #pragma unroll
        for (int nt = 0; nt < 8; nt++) {
            const int m = b0 + wm + mt * 16 + g;
            const int n = j0 + wn + nt * 8 + 2 * tg;
            *reinterpret_cast<float2*>(&out[(long)m * OUT_COUNT + n]) =
                make_float2(acc[mt][nt][0], acc[mt][nt][1]);
            *reinterpret_cast<float2*>(&out[(long)(m + 8) * OUT_COUNT + n]) =
                make_float2(acc[mt][nt][2], acc[mt][nt][3]);
        }
    }
}

// ===================== launch =====================
extern "C" void kernel_launch(void* const* d_in, const int* in_sizes, int n_in,
                              void* d_out, int out_size) {
    const float* x       = (const float*)d_in[0];
    const float* coeffs  = (const float*)d_in[1];
    const float* centers = (const float*)d_in[2];
    const float* slopes  = (const float*)d_in[3];
    float* out = (float*)d_out;

    cudaFuncSetAttribute(tanh_basis_mma_kernel,
                         cudaFuncAttributeMaxDynamicSharedMemorySize, SMEM_BYTES);

    split_coeffs_kernel<<<(OUT_COUNT * KTOT / 4) / 256, 256>>>(coeffs);

    dim3 grid(BATCH / BM, OUT_COUNT / BN);   // 64 x 2 = 128 CTAs = one wave
    tanh_basis_mma_kernel<<<grid, 512, SMEM_BYTES>>>(x, centers, slopes, out);
}

// round 13
// speedup vs baseline: 4.3369x; 1.2559x over previous
#include <cuda_runtime.h>
#include <cuda_fp16.h>
#include <cstdint>

#define IN_COUNT 512
#define NB 8
#define OUT_COUNT 512
#define BATCH 8192
#define KTOT 4096            // 512 * 8
#define BK 32                // 4 input features x 8 bases per chunk
#define NCHUNK (KTOT / BK)   // 128
#define BM 128
#define BN 256

#define PITCH 40                         // fp16 elems per smem row (80B) -> conflict-free frag LDS
#define TILE_A_BYTES (128 * PITCH * 2)   // 10240
#define TILE_B_BYTES (256 * PITCH * 2)   // 20480
#define OFF_A  0
#define OFF_BH (TILE_A_BYTES)
#define OFF_BL (TILE_A_BYTES + TILE_B_BYTES)
#define STAGE_BYTES (TILE_A_BYTES + 2 * TILE_B_BYTES)   // 51200
#define SMEM_BYTES (2 * STAGE_BYTES)                    // 102400

// ---- device scratch: fp16 hi/lo split of coeffs, [N=512][K=4096] K-major ----
__device__ __align__(16) __half g_ch[OUT_COUNT * KTOT];
__device__ __align__(16) __half g_cl[OUT_COUNT * KTOT];

// ===================== helpers =====================
__device__ __forceinline__ uint32_t smem_u32(const void* p) {
    uint32_t a;
    asm("{ .reg .u64 t; cvta.to.shared.u64 t, %1; cvt.u32.u64 %0, t; }" : "=r"(a) : "l"(p));
    return a;
}
__device__ __forceinline__ float ex2(float x) {
    float y; asm("ex2.approx.f32 %0, %1;" : "=f"(y) : "f"(x)); return y;
}
__device__ __forceinline__ float frcp(float x) {
    float y; asm("rcp.approx.f32 %0, %1;" : "=f"(y) : "f"(x)); return y;
}
__device__ __forceinline__ void cp16(uint32_t dst_smem, const void* src) {
    asm volatile("cp.async.cg.shared.global [%0], [%1], 16;" :: "r"(dst_smem), "l"(src) : "memory");
}
__device__ __forceinline__ void mma16816(float* d, const uint32_t* a, const uint32_t* b) {
    asm volatile(
        "mma.sync.aligned.m16n8k16.row.col.f32.f16.f16.f32 "
        "{%0,%1,%2,%3}, {%4,%5,%6,%7}, {%8,%9}, {%0,%1,%2,%3};"
        : "+f"(d[0]), "+f"(d[1]), "+f"(d[2]), "+f"(d[3])
        : "r"(a[0]), "r"(a[1]), "r"(a[2]), "r"(a[3]), "r"(b[0]), "r"(b[1]));
}

// ===================== kernel 1: split coeffs into fp16 hi/lo =====================
__global__ void split_coeffs_kernel(const float* __restrict__ c) {
    int idx = blockIdx.x * blockDim.x + threadIdx.x;   // 512*4096/4 = 524288 float4 groups
    float4 v = reinterpret_cast<const float4*>(c)[idx];
    __half2 h0 = __floats2half2_rn(v.x, v.y);          // low half = v.x (lower address)
    __half2 h1 = __floats2half2_rn(v.z, v.w);
    float rx = v.x - __low2float(h0),  ry = v.y - __high2float(h0);
    float rz = v.z - __low2float(h1),  rw = v.w - __high2float(h1);
    __half2 l0 = __floats2half2_rn(rx, ry);
    __half2 l1 = __floats2half2_rn(rz, rw);
    reinterpret_cast<uint2*>(g_ch)[idx] =
        make_uint2(*reinterpret_cast<uint32_t*>(&h0), *reinterpret_cast<uint32_t*>(&h1));
    reinterpret_cast<uint2*>(g_cl)[idx] =
        make_uint2(*reinterpret_cast<uint32_t*>(&l0), *reinterpret_cast<uint32_t*>(&l1));
}

// ===================== kernel 2: fused basis + asym-split fp16 mma.sync GEMM =====================
__global__ __launch_bounds__(512, 1)
void tanh_basis_mma_kernel(const float* __restrict__ x,
                           const float* __restrict__ centers,
                           const float* __restrict__ slopes,
                           float* __restrict__ out)
{
    extern __shared__ char smem[];
    const int tid  = threadIdx.x;
    const int lane = tid & 31;
    const int wid  = tid >> 5;          // 0..15
    const int g    = lane >> 2;         // fragment group id
    const int tg   = lane & 3;          // thread-in-group
    const int wm   = (wid & 3) * 32;    // 4 warps over M (128)
    const int wn   = (wid >> 2) * 64;   // 4 warps over N (256)
    const int b0   = blockIdx.x * BM;
    const int j0   = blockIdx.y * BN;

    const int il = tid & 3;             // feature lane within chunk (4 features)
    const int rb = tid >> 2;            // 0..127: one A row per thread

    float acc[2][8][4];
    #pragma unroll
    for (int mt = 0; mt < 2; mt++)
        #pragma unroll
        for (int nt = 0; nt < 8; nt++)
            #pragma unroll
            for (int q = 0; q < 4; q++) acc[mt][nt][q] = 0.f;

    char* stg0 = smem;
    char* stg1 = smem + STAGE_BYTES;
    const float NEG2LOG2E = -2.885390081777927f;   // -2 * log2(e)

    uint32_t hp[4];                     // staged basis regs (one row per thread, fp16x2 x4)

    // ---- stage B (coeff hi/lo) for chunk c via cp.async ----
    auto stage_B = [&](int c, char* stage) {
        uint32_t dH = smem_u32(stage) + OFF_BH;
        uint32_t dL = smem_u32(stage) + OFF_BL;
        #pragma unroll
        for (int r = 0; r < 2; r++) {
            int slot = r * 512 + tid;              // 1024 slots of 16B per array
            int n = slot >> 2, kq = slot & 3;
            long go = (long)(j0 + n) * KTOT + c * BK + kq * 8;
            uint32_t doff = (uint32_t)(n * (PITCH * 2) + kq * 16);
            cp16(dH + doff, g_ch + go);
            cp16(dL + doff, g_cl + go);
        }
        asm volatile("cp.async.commit_group;" ::: "memory");
    };

    // ---- compute basis chunk c (sigmoid) into hp registers (fp16) ----
    auto compute_basis = [&](int c) {
        const int i = c * 4 + il;
        const float4 ct0 = __ldg(reinterpret_cast<const float4*>(&centers[i * NB]));
        const float4 ct1 = __ldg(reinterpret_cast<const float4*>(&centers[i * NB + 4]));
        const float4 sl0 = __ldg(reinterpret_cast<const float4*>(&slopes[i * NB]));
        const float4 sl1 = __ldg(reinterpret_cast<const float4*>(&slopes[i * NB + 4]));
        float km[8] = { NEG2LOG2E * sl0.x, NEG2LOG2E * sl0.y, NEG2LOG2E * sl0.z, NEG2LOG2E * sl0.w,
                        NEG2LOG2E * sl1.x, NEG2LOG2E * sl1.y, NEG2LOG2E * sl1.z, NEG2LOG2E * sl1.w };
        float kc[8] = { -km[0] * ct0.x, -km[1] * ct0.y, -km[2] * ct0.z, -km[3] * ct0.w,
                        -km[4] * ct1.x, -km[5] * ct1.y, -km[6] * ct1.z, -km[7] * ct1.w };
        const float xv = __ldg(&x[(long)(b0 + rb) * IN_COUNT + i]);
        float sv[8];
        #pragma unroll
        for (int m = 0; m < 8; m++) {
            float e = ex2(fmaf(km[m], xv, kc[m]));     // exp(-2*gamma*(x-c))
            sv[m] = frcp(1.0f + e);                     // sigmoid
        }
        #pragma unroll
        for (int q = 0; q < 4; q++) {
            __half2 h = __floats2half2_rn(sv[2 * q], sv[2 * q + 1]);
            hp[q] = *reinterpret_cast<uint32_t*>(&h);
        }
    };

    // ---- store staged basis into stage SMEM ----
    auto store_basis = [&](char* stage) {
        uint32_t doff = (uint32_t)(rb * (PITCH * 2) + il * 16);
        *reinterpret_cast<uint4*>(stage + OFF_A + doff) = make_uint4(hp[0], hp[1], hp[2], hp[3]);
    };

    // ---- MMA over one BK=32 stage (2 k16 steps), 2 phases (A*Bh, A*Bl) ----
    auto do_mma = [&](char* stage) {
        #pragma unroll
        for (int kk = 0; kk < 2; kk++) {
            const int kbB = kk * 32;        // byte offset along k
            uint32_t aH[2][4];
            #pragma unroll
            for (int mt = 0; mt < 2; mt++) {
                const int m0 = wm + mt * 16;
                const char* pH = stage + OFF_A + (m0 + g) * (PITCH * 2) + tg * 4 + kbB;
                aH[mt][0] = *(const uint32_t*)(pH);
                aH[mt][1] = *(const uint32_t*)(pH + 8 * (PITCH * 2));
                aH[mt][2] = *(const uint32_t*)(pH + 16);
                aH[mt][3] = *(const uint32_t*)(pH + 8 * (PITCH * 2) + 16);
            }
            // phase 1: A * B_hi over all nt (16 independent MMAs)
            #pragma unroll
            for (int nt = 0; nt < 8; nt++) {
                const char* qH = stage + OFF_BH + (wn + nt * 8 + g) * (PITCH * 2) + tg * 4 + kbB;
                uint32_t bH[2] = { *(const uint32_t*)(qH), *(const uint32_t*)(qH + 16) };
                mma16816(acc[0][nt], aH[0], bH);
                mma16816(acc[1][nt], aH[1], bH);
            }
            // phase 2: A * B_lo
            #pragma unroll
            for (int nt = 0; nt < 8; nt++) {
                const char* qL = stage + OFF_BL + (wn + nt * 8 + g) * (PITCH * 2) + tg * 4 + kbB;
                uint32_t bL[2] = { *(const uint32_t*)(qL), *(const uint32_t*)(qL + 16) };
                mma16816(acc[0][nt], aH[0], bL);
                mma16816(acc[1][nt], aH[1], bL);
            }
        }
    };

    // ---- prologue: fill stage 0 ----
    stage_B(0, stg0);
    compute_basis(0);
    store_basis(stg0);
    asm volatile("cp.async.wait_group 0;" ::: "memory");
    __syncthreads();

    // ---- main loop ----
    for (int c = 0; c < NCHUNK; c++) {
        char* cur = (c & 1) ? stg1 : stg0;
        char* nxt = (c & 1) ? stg0 : stg1;
        if (c + 1 < NCHUNK) {
            stage_B(c + 1, nxt);     // async loads fly during MMA
            compute_basis(c + 1);    // MUFU overlaps HMMA
        }
        do_mma(cur);
        if (c + 1 < NCHUNK) {
            store_basis(nxt);
            asm volatile("cp.async.wait_group 0;" ::: "memory");
        }
        __syncthreads();
    }

    // ---- epilogue: write fp32 accumulators ----
    #pragma unroll
    for (int mt = 0; mt < 2; mt++) {
        #pragma unroll
        for (int nt = 0; nt < 8; nt++) {
            const int m = b0 + wm + mt * 16 + g;
            const int n = j0 + wn + nt * 8 + 2 * tg;
            *reinterpret_cast<float2*>(&out[(long)m * OUT_COUNT + n]) =
                make_float2(acc[mt][nt][0], acc[mt][nt][1]);
            *reinterpret_cast<float2*>(&out[(long)(m + 8) * OUT_COUNT + n]) =
                make_float2(acc[mt][nt][2], acc[mt][nt][3]);
        }
    }
}

// ===================== launch =====================
extern "C" void kernel_launch(void* const* d_in, const int* in_sizes, int n_in,
                              void* d_out, int out_size) {
    const float* x       = (const float*)d_in[0];
    const float* coeffs  = (const float*)d_in[1];
    const float* centers = (const float*)d_in[2];
    const float* slopes  = (const float*)d_in[3];
    float* out = (float*)d_out;

    cudaFuncSetAttribute(tanh_basis_mma_kernel,
                         cudaFuncAttributeMaxDynamicSharedMemorySize, SMEM_BYTES);

    split_coeffs_kernel<<<(OUT_COUNT * KTOT / 4) / 256, 256>>>(coeffs);

    dim3 grid(BATCH / BM, OUT_COUNT / BN);   // 64 x 2 = 128 CTAs = one wave
    tanh_basis_mma_kernel<<<grid, 512, SMEM_BYTES>>>(x, centers, slopes, out);
}